// round 2
// baseline (speedup 1.0000x reference)
#include <cuda_runtime.h>
#include <cuda_bf16.h>
#include <cstdint>
#include <math.h>

// ---------------------------------------------------------------------------
// GroupedGLU via mma.sync (HMMA) bf16x3-split GEMMs.
// tcgen05 is unavailable: harness PTX target is compute_103 (no 'a' features).
// Pipeline:
//   xsplit:  x fp32 -> x_hi/x_lo bf16
//   tsplit:  W fp32 [R][C] -> W^T bf16 hi/lo [C][R]   (3 weights)
//   gemm1:   z_gate,z_up = x @ Wg, x @ Wu ; h = silu(zg)*zu -> h_hi/h_lo bf16
//   gemm2:   y = h @ Wd -> fp32 out
// Each GEMM: 3 passes a_hi*b_hi + a_lo*b_hi + a_hi*b_lo  (drops lo*lo ~ 2^-16)
// ---------------------------------------------------------------------------

#define T_TOK   131072
#define DMODEL  256
#define DFF_    1024
#define NG      8
#define TPG     (T_TOK / NG)
#define SA      72          // smem row stride in bf16 elems (64 data + 8 pad)

__device__ __nv_bfloat16 g_x_hi[(size_t)T_TOK * DMODEL];
__device__ __nv_bfloat16 g_x_lo[(size_t)T_TOK * DMODEL];
__device__ __nv_bfloat16 g_h_hi[(size_t)T_TOK * DFF_];
__device__ __nv_bfloat16 g_h_lo[(size_t)T_TOK * DFF_];
__device__ __nv_bfloat16 g_wg_hi[(size_t)NG * DFF_ * DMODEL];
__device__ __nv_bfloat16 g_wg_lo[(size_t)NG * DFF_ * DMODEL];
__device__ __nv_bfloat16 g_wu_hi[(size_t)NG * DFF_ * DMODEL];
__device__ __nv_bfloat16 g_wu_lo[(size_t)NG * DFF_ * DMODEL];
__device__ __nv_bfloat16 g_wd_hi[(size_t)NG * DMODEL * DFF_];
__device__ __nv_bfloat16 g_wd_lo[(size_t)NG * DMODEL * DFF_];

// ------------------------------- helpers -----------------------------------

__device__ __forceinline__ uint32_t smaddr(const void* p) {
    return (uint32_t)__cvta_generic_to_shared(p);
}

__device__ __forceinline__ void cp16(uint32_t dst, const void* src) {
    asm volatile("cp.async.cg.shared.global [%0], [%1], 16;" :: "r"(dst), "l"(src));
}
#define CP_COMMIT() asm volatile("cp.async.commit_group;" ::: "memory")
#define CP_WAIT1()  asm volatile("cp.async.wait_group 1;" ::: "memory")
#define CP_WAIT0()  asm volatile("cp.async.wait_group 0;" ::: "memory")

// D = A(16x16 bf16) * B(16x8 bf16) + D, fp32 accum
__device__ __forceinline__ void mma16816(float* c, const uint32_t* a,
                                         uint32_t b0, uint32_t b1) {
    asm volatile(
        "mma.sync.aligned.m16n8k16.row.col.f32.bf16.bf16.f32 "
        "{%0,%1,%2,%3}, {%4,%5,%6,%7}, {%8,%9}, {%0,%1,%2,%3};"
        : "+f"(c[0]), "+f"(c[1]), "+f"(c[2]), "+f"(c[3])
        : "r"(a[0]), "r"(a[1]), "r"(a[2]), "r"(a[3]), "r"(b0), "r"(b1));
}

__device__ __forceinline__ void split2(float vx, float vy, uint32_t& hi, uint32_t& lo) {
    __nv_bfloat16 hx = __float2bfloat16(vx);
    __nv_bfloat16 hy = __float2bfloat16(vy);
    float rx = vx - __bfloat162float(hx);
    float ry = vy - __bfloat162float(hy);
    __nv_bfloat16 lx = __float2bfloat16(rx);
    __nv_bfloat16 ly = __float2bfloat16(ry);
    hi = ((uint32_t)__bfloat16_as_ushort(hy) << 16) | (uint32_t)__bfloat16_as_ushort(hx);
    lo = ((uint32_t)__bfloat16_as_ushort(ly) << 16) | (uint32_t)__bfloat16_as_ushort(lx);
}

__device__ __forceinline__ float silu_f(float z) {
    return z / (1.0f + __expf(-z));
}

// --------------------------- prolog kernels --------------------------------

__global__ void xsplit_kernel(const float* __restrict__ x) {
    size_t i = ((size_t)blockIdx.x * 256 + threadIdx.x) * 2;
    float2 v = *(const float2*)&x[i];
    uint32_t hi, lo; split2(v.x, v.y, hi, lo);
    *(uint32_t*)&g_x_hi[i] = hi;
    *(uint32_t*)&g_x_lo[i] = lo;
}

// in: [g][R][C] fp32 -> out: [g][C][R] bf16 hi/lo (transpose + split)
__global__ void tsplit_kernel(const float* __restrict__ in, int which, int R, int C) {
    __nv_bfloat16 *oh, *ol;
    if (which == 0)      { oh = g_wg_hi; ol = g_wg_lo; }
    else if (which == 1) { oh = g_wu_hi; ol = g_wu_lo; }
    else                 { oh = g_wd_hi; ol = g_wd_lo; }
    __shared__ float tile[32][33];
    int g = blockIdx.z;
    const float* src = in + (size_t)g * R * C;
    __nv_bfloat16* dh = oh + (size_t)g * R * C;
    __nv_bfloat16* dl = ol + (size_t)g * R * C;
    int c0 = blockIdx.x * 32, r0 = blockIdx.y * 32;
    int tx = threadIdx.x, ty = threadIdx.y;
    #pragma unroll
    for (int j = ty; j < 32; j += 8)
        tile[j][tx] = src[(size_t)(r0 + j) * C + c0 + tx];
    __syncthreads();
    #pragma unroll
    for (int j = ty; j < 32; j += 8) {
        float v = tile[tx][j];
        __nv_bfloat16 h = __float2bfloat16(v);
        float r = v - __bfloat162float(h);
        size_t o = (size_t)(c0 + j) * R + r0 + tx;
        dh[o] = h;
        dl[o] = __float2bfloat16(r);
    }
}

// --------------------------- GEMM1: gate/up --------------------------------
// block tile: 128 tokens x 64 dff (gate AND up), K=256 in 4 chunks of 64,
// 8 warps as 4(M) x 2(N). smem per buffer (bf16 elems):
//   A_hi 0 (128*72), A_lo 9216, Bg_hi 18432 (64*72), Bg_lo 23040,
//   Bu_hi 27648, Bu_lo 32256; buffer = 36864 elems = 73728 B, double buffered.
#define G1_BUF 36864
#define G1_SMEM (2 * G1_BUF * 2)

__global__ void __launch_bounds__(256, 1) gemm1_kernel() {
    extern __shared__ __align__(16) __nv_bfloat16 sm[];
    const int tid  = threadIdx.x;
    const int lane = tid & 31, w = tid >> 5;
    const int wm = w & 3, wn = w >> 2;
    const int gID = lane >> 2, tig = lane & 3;
    const int m0 = blockIdx.y * 128;
    const int n0 = blockIdx.x * 64;
    const int g  = m0 / TPG;

    const __nv_bfloat16* wgh = g_wg_hi + ((size_t)g * DFF_ + n0) * DMODEL;
    const __nv_bfloat16* wgl = g_wg_lo + ((size_t)g * DFF_ + n0) * DMODEL;
    const __nv_bfloat16* wuh = g_wu_hi + ((size_t)g * DFF_ + n0) * DMODEL;
    const __nv_bfloat16* wul = g_wu_lo + ((size_t)g * DFF_ + n0) * DMODEL;

    float cg[2][4][4] = {}, cu[2][4][4] = {};

    auto issue = [&](int kc) {
        __nv_bfloat16* buf = sm + (kc & 1) * G1_BUF;
        const int k0g = kc * 64;
        #pragma unroll
        for (int t = 0; t < 4; t++) {
            int gi = tid + t * 256;
            int row = gi >> 3, seg = gi & 7;
            size_t so = (size_t)(m0 + row) * DMODEL + k0g + seg * 8;
            uint32_t d = smaddr(buf + row * SA + seg * 8);
            cp16(d, g_x_hi + so);
            cp16(d + 9216 * 2, g_x_lo + so);
        }
        #pragma unroll
        for (int t = 0; t < 2; t++) {
            int gi = tid + t * 256;
            int row = gi >> 3, seg = gi & 7;
            size_t so = (size_t)row * DMODEL + k0g + seg * 8;
            uint32_t d = smaddr(buf + 18432 + row * SA + seg * 8);
            cp16(d,            wgh + so);
            cp16(d + 4608 * 2, wgl + so);
            cp16(d + 9216 * 2, wuh + so);
            cp16(d + 13824 * 2, wul + so);
        }
    };

    auto compute = [&](int kc) {
        const __nv_bfloat16* buf = sm + (kc & 1) * G1_BUF;
        const __nv_bfloat16* Ah = buf;
        const __nv_bfloat16* Al = buf + 9216;
        const __nv_bfloat16* Bb = buf + 18432;
        #pragma unroll
        for (int k16 = 0; k16 < 4; k16++) {
            const int k0 = k16 * 16;
            uint32_t ah[2][4], al[2][4];
            #pragma unroll
            for (int mf = 0; mf < 2; mf++) {
                int m = wm * 32 + mf * 16 + gID;
                const __nv_bfloat16* p = Ah + m * SA + k0 + tig * 2;
                ah[mf][0] = *(const uint32_t*)p;
                ah[mf][1] = *(const uint32_t*)(p + 8 * SA);
                ah[mf][2] = *(const uint32_t*)(p + 8);
                ah[mf][3] = *(const uint32_t*)(p + 8 * SA + 8);
                const __nv_bfloat16* q = Al + m * SA + k0 + tig * 2;
                al[mf][0] = *(const uint32_t*)q;
                al[mf][1] = *(const uint32_t*)(q + 8 * SA);
                al[mf][2] = *(const uint32_t*)(q + 8);
                al[mf][3] = *(const uint32_t*)(q + 8 * SA + 8);
            }
            #pragma unroll
            for (int nf = 0; nf < 4; nf++) {
                int n = wn * 32 + nf * 8 + gID;
                const __nv_bfloat16* q = Bb + n * SA + k0 + tig * 2;
                uint32_t bgh0 = *(const uint32_t*)q;
                uint32_t bgh1 = *(const uint32_t*)(q + 8);
                uint32_t bgl0 = *(const uint32_t*)(q + 4608);
                uint32_t bgl1 = *(const uint32_t*)(q + 4608 + 8);
                uint32_t buh0 = *(const uint32_t*)(q + 9216);
                uint32_t buh1 = *(const uint32_t*)(q + 9216 + 8);
                uint32_t bul0 = *(const uint32_t*)(q + 13824);
                uint32_t bul1 = *(const uint32_t*)(q + 13824 + 8);
                #pragma unroll
                for (int mf = 0; mf < 2; mf++) {
                    mma16816(cg[mf][nf], ah[mf], bgh0, bgh1);
                    mma16816(cg[mf][nf], al[mf], bgh0, bgh1);
                    mma16816(cg[mf][nf], ah[mf], bgl0, bgl1);
                    mma16816(cu[mf][nf], ah[mf], buh0, buh1);
                    mma16816(cu[mf][nf], al[mf], buh0, buh1);
                    mma16816(cu[mf][nf], ah[mf], bul0, bul1);
                }
            }
        }
    };

    issue(0); CP_COMMIT();
    #pragma unroll 1
    for (int kc = 0; kc < 4; kc++) {
        if (kc < 3) { issue(kc + 1); CP_COMMIT(); CP_WAIT1(); }
        else        { CP_WAIT0(); }
        __syncthreads();
        compute(kc);
        __syncthreads();
    }

    // epilogue: h = silu(zg)*zu, split to bf16 hi/lo, store
    #pragma unroll
    for (int mf = 0; mf < 2; mf++) {
        #pragma unroll
        for (int nf = 0; nf < 4; nf++) {
            int r0 = m0 + wm * 32 + mf * 16 + gID;
            int c0 = n0 + wn * 32 + nf * 8 + tig * 2;
            float h0 = silu_f(cg[mf][nf][0]) * cu[mf][nf][0];
            float h1 = silu_f(cg[mf][nf][1]) * cu[mf][nf][1];
            float h2 = silu_f(cg[mf][nf][2]) * cu[mf][nf][2];
            float h3 = silu_f(cg[mf][nf][3]) * cu[mf][nf][3];
            uint32_t hi, lo;
            split2(h0, h1, hi, lo);
            *(uint32_t*)&g_h_hi[(size_t)r0 * DFF_ + c0] = hi;
            *(uint32_t*)&g_h_lo[(size_t)r0 * DFF_ + c0] = lo;
            split2(h2, h3, hi, lo);
            *(uint32_t*)&g_h_hi[(size_t)(r0 + 8) * DFF_ + c0] = hi;
            *(uint32_t*)&g_h_lo[(size_t)(r0 + 8) * DFF_ + c0] = lo;
        }
    }
}

// ----------------------------- GEMM2: down ---------------------------------
// block tile: 128 tokens x 128 dmodel, K=1024 in 16 chunks of 64,
// 8 warps as 4(M) x 2(N) (warp N = 64). smem per buffer (bf16 elems):
//   A_hi 0 (128*72), A_lo 9216, B_hi 18432 (128*72), B_lo 27648; buf 36864.
#define G2_BUF 36864
#define G2_SMEM (2 * G2_BUF * 2)

__global__ void __launch_bounds__(256, 1) gemm2_kernel(float* __restrict__ out) {
    extern __shared__ __align__(16) __nv_bfloat16 sm[];
    const int tid  = threadIdx.x;
    const int lane = tid & 31, w = tid >> 5;
    const int wm = w & 3, wn = w >> 2;
    const int gID = lane >> 2, tig = lane & 3;
    const int m0 = blockIdx.y * 128;
    const int n0 = blockIdx.x * 128;
    const int g  = m0 / TPG;

    const __nv_bfloat16* wdh = g_wd_hi + ((size_t)g * DMODEL + n0) * DFF_;
    const __nv_bfloat16* wdl = g_wd_lo + ((size_t)g * DMODEL + n0) * DFF_;

    float c[2][8][4] = {};

    auto issue = [&](int kc) {
        __nv_bfloat16* buf = sm + (kc & 1) * G2_BUF;
        const int k0g = kc * 64;
        #pragma unroll
        for (int t = 0; t < 4; t++) {
            int gi = tid + t * 256;
            int row = gi >> 3, seg = gi & 7;
            size_t soA = (size_t)(m0 + row) * DFF_ + k0g + seg * 8;
            uint32_t dA = smaddr(buf + row * SA + seg * 8);
            cp16(dA, g_h_hi + soA);
            cp16(dA + 9216 * 2, g_h_lo + soA);
            size_t soB = (size_t)row * DFF_ + k0g + seg * 8;
            uint32_t dB = smaddr(buf + 18432 + row * SA + seg * 8);
            cp16(dB, wdh + soB);
            cp16(dB + 9216 * 2, wdl + soB);
        }
    };

    auto compute = [&](int kc) {
        const __nv_bfloat16* buf = sm + (kc & 1) * G2_BUF;
        const __nv_bfloat16* Ah = buf;
        const __nv_bfloat16* Al = buf + 9216;
        const __nv_bfloat16* Bh = buf + 18432;
        const __nv_bfloat16* Bl = buf + 27648;
        #pragma unroll
        for (int k16 = 0; k16 < 4; k16++) {
            const int k0 = k16 * 16;
            uint32_t ah[2][4], al[2][4];
            #pragma unroll
            for (int mf = 0; mf < 2; mf++) {
                int m = wm * 32 + mf * 16 + gID;
                const __nv_bfloat16* p = Ah + m * SA + k0 + tig * 2;
                ah[mf][0] = *(const uint32_t*)p;
                ah[mf][1] = *(const uint32_t*)(p + 8 * SA);
                ah[mf][2] = *(const uint32_t*)(p + 8);
                ah[mf][3] = *(const uint32_t*)(p + 8 * SA + 8);
                const __nv_bfloat16* q = Al + m * SA + k0 + tig * 2;
                al[mf][0] = *(const uint32_t*)q;
                al[mf][1] = *(const uint32_t*)(q + 8 * SA);
                al[mf][2] = *(const uint32_t*)(q + 8);
                al[mf][3] = *(const uint32_t*)(q + 8 * SA + 8);
            }
            #pragma unroll
            for (int nf = 0; nf < 8; nf++) {
                int n = wn * 64 + nf * 8 + gID;
                const __nv_bfloat16* qh = Bh + n * SA + k0 + tig * 2;
                const __nv_bfloat16* ql = Bl + n * SA + k0 + tig * 2;
                uint32_t bh0 = *(const uint32_t*)qh;
                uint32_t bh1 = *(const uint32_t*)(qh + 8);
                uint32_t bl0 = *(const uint32_t*)ql;
                uint32_t bl1 = *(const uint32_t*)(ql + 8);
                #pragma unroll
                for (int mf = 0; mf < 2; mf++) {
                    mma16816(c[mf][nf], ah[mf], bh0, bh1);
                    mma16816(c[mf][nf], al[mf], bh0, bh1);
                    mma16816(c[mf][nf], ah[mf], bl0, bl1);
                }
            }
        }
    };

    issue(0); CP_COMMIT();
    #pragma unroll 1
    for (int kc = 0; kc < 16; kc++) {
        if (kc < 15) { issue(kc + 1); CP_COMMIT(); CP_WAIT1(); }
        else         { CP_WAIT0(); }
        __syncthreads();
        compute(kc);
        __syncthreads();
    }

    #pragma unroll
    for (int mf = 0; mf < 2; mf++) {
        #pragma unroll
        for (int nf = 0; nf < 8; nf++) {
            int r0 = m0 + wm * 32 + mf * 16 + gID;
            int c0 = n0 + wn * 64 + nf * 8 + tig * 2;
            float2 v0 = { c[mf][nf][0], c[mf][nf][1] };
            float2 v1 = { c[mf][nf][2], c[mf][nf][3] };
            *(float2*)&out[(size_t)r0 * DMODEL + c0] = v0;
            *(float2*)&out[(size_t)(r0 + 8) * DMODEL + c0] = v1;
        }
    }
}

// ------------------------------- launch -------------------------------------
extern "C" void kernel_launch(void* const* d_in, const int* in_sizes, int n_in,
                              void* d_out, int out_size) {
    const float* x  = (const float*)d_in[0];
    const float* wg = (const float*)d_in[1];
    const float* wu = (const float*)d_in[2];
    const float* wd = (const float*)d_in[3];
    // d_in[4] = offs: uniform groups by construction (reference reshapes by T/G)

    cudaFuncSetAttribute(gemm1_kernel, cudaFuncAttributeMaxDynamicSharedMemorySize, G1_SMEM);
    cudaFuncSetAttribute(gemm2_kernel, cudaFuncAttributeMaxDynamicSharedMemorySize, G2_SMEM);

    xsplit_kernel<<<T_TOK * DMODEL / 512, 256>>>(x);
    dim3 tb(32, 8);
    tsplit_kernel<<<dim3(DFF_ / 32, DMODEL / 32, NG), tb>>>(wg, 0, DMODEL, DFF_);
    tsplit_kernel<<<dim3(DFF_ / 32, DMODEL / 32, NG), tb>>>(wu, 1, DMODEL, DFF_);
    tsplit_kernel<<<dim3(DMODEL / 32, DFF_ / 32, NG), tb>>>(wd, 2, DFF_, DMODEL);

    gemm1_kernel<<<dim3(DFF_ / 64, T_TOK / 128), 256, G1_SMEM>>>();
    gemm2_kernel<<<dim3(DMODEL / 128, T_TOK / 128), 256, G2_SMEM>>>((float*)d_out);
}